// round 9
// baseline (speedup 1.0000x reference)
#include <cuda_runtime.h>
#include <math.h>
#include <stdint.h>

#define N_NODES 100000
#define NE      1000000
#define DIM     64
#define TM      128          // edges per CTA in fused kernel
#define AST     68           // A tile row stride (floats): bank-conflict-free quads
#define WST     72           // W tile row stride (floats): conflict-free B-frag loads

// ---------------- scratch (allocation-free rule) ----------------
__device__ float g_node_sum[(size_t)N_NODES * DIM];   // 25.6 MB
__device__ float g_deg[N_NODES];
__device__ int   g_is64;

// ---------------- dtype probe (proven round 3) ----------------
__global__ void detect_kernel(const int* __restrict__ idx32) {
    __shared__ int any_nonzero;
    if (threadIdx.x == 0) any_nonzero = 0;
    __syncthreads();
    int t = threadIdx.x;
    #pragma unroll
    for (int i = 0; i < 4; ++i) {
        int pos = 2 * (t + i * 256) + 1;
        if (idx32[pos] != 0) any_nonzero = 1;
    }
    __syncthreads();
    if (threadIdx.x == 0) g_is64 = any_nonzero ? 0 : 1;
}

__device__ __forceinline__ int load_index(const void* idx, long long pos, int is64) {
    long long r = is64 ? ((const long long*)idx)[pos]
                       : (long long)((const int*)idx)[pos];
    if (r < 0) r = 0;
    if (r >= N_NODES) r = N_NODES - 1;
    return (int)r;
}

__global__ void zero_kernel() {
    size_t i = (size_t)blockIdx.x * blockDim.x + threadIdx.x;
    float4 z = make_float4(0.f, 0.f, 0.f, 0.f);
    if (i < (size_t)N_NODES * DIM / 4)
        reinterpret_cast<float4*>(g_node_sum)[i] = z;
    if (i < N_NODES / 4)
        reinterpret_cast<float4*>(g_deg)[i] = z;
}

// ---------------- scatter (proven round 3) ----------------
__global__ void scatter_kernel(const float* __restrict__ emb,
                               const void* __restrict__ idx) {
    const int is64 = g_is64;
    int t = blockIdx.x * blockDim.x + threadIdx.x;
    int e = t >> 4;
    if (e >= NE) return;
    int q = t & 15;
    int u = load_index(idx, 2LL * e, is64);
    int v = load_index(idx, 2LL * e + 1, is64);
    float4 val = reinterpret_cast<const float4*>(emb)[e * 16 + q];
    float* pu = g_node_sum + (size_t)u * DIM + q * 4;
    float* pv = g_node_sum + (size_t)v * DIM + q * 4;
    asm volatile("red.global.add.v4.f32 [%0], {%1, %2, %3, %4};"
                 :: "l"(pu), "f"(val.x), "f"(val.y), "f"(val.z), "f"(val.w)
                 : "memory");
    asm volatile("red.global.add.v4.f32 [%0], {%1, %2, %3, %4};"
                 :: "l"(pv), "f"(val.x), "f"(val.y), "f"(val.z), "f"(val.w)
                 : "memory");
    if (q == 0) {
        atomicAdd(&g_deg[u], 1.0f);
        atomicAdd(&g_deg[v], 1.0f);
    }
}

// ---------------- mma.sync tf32 helpers (target-neutral PTX) ----------------
__device__ __forceinline__ float tf32r(float x) {
    uint32_t u;
    asm("cvt.rna.tf32.f32 %0, %1;" : "=r"(u) : "f"(x));
    return __uint_as_float(u);
}
__device__ __forceinline__ void mma8(float* d, const uint32_t* a, const uint32_t* b) {
    asm volatile(
        "mma.sync.aligned.m16n8k8.row.col.f32.tf32.tf32.f32 "
        "{%0,%1,%2,%3}, {%4,%5,%6,%7}, {%8,%9}, {%0,%1,%2,%3};"
        : "+f"(d[0]), "+f"(d[1]), "+f"(d[2]), "+f"(d[3])
        : "r"(a[0]), "r"(a[1]), "r"(a[2]), "r"(a[3]), "r"(b[0]), "r"(b[1]));
}

// ---------------- fused kernel: tf32 mma.sync dual GEMM ----------------
// smem floats: sAu[128][AST], sAv[128][AST], sWf[64][WST], sWb[64][WST],
//              sBf[64], sBb[64], sWg[64]   => 26816 floats = 107264 B
__global__ __launch_bounds__(256, 2)
void fused_kernel(const float* __restrict__ emb,
                  const float* __restrict__ Wf, const float* __restrict__ bf,
                  const float* __restrict__ Wb, const float* __restrict__ bb,
                  const float* __restrict__ Wg, const float* __restrict__ bg,
                  const void* __restrict__ idx,
                  float* __restrict__ out) {
    extern __shared__ float sm[];
    float* sAu = sm;                       // also reused for af accums
    float* sAv = sAu + TM * AST;           // also reused for ab accums
    float* sWf = sAv + TM * AST;
    float* sWb = sWf + DIM * WST;
    float* sBf = sWb + DIM * WST;
    float* sBb = sBf + DIM;
    float* sWg = sBb + DIM;

    const int tid  = threadIdx.x;
    const int lane = tid & 31;
    const int wid  = tid >> 5;
    const int is64 = g_is64;

    // Stage weights (tf32-rounded), biases, gate vector
    #pragma unroll
    for (int i = 0; i < 16; ++i) {
        int lin = tid + i * 256;
        int k = lin >> 6, n = lin & 63;
        sWf[k * WST + n] = tf32r(Wf[lin]);
        sWb[k * WST + n] = tf32r(Wb[lin]);
    }
    if (tid < DIM) {
        sBf[tid] = bf[tid];
        sBb[tid] = bb[tid];
        sWg[tid] = Wg[tid];
    }

    // Build A tiles (tf32-rounded): 2 threads per edge, 32 dims each
    {
        int le = tid >> 1;
        int e  = blockIdx.x * TM + le;
        if (e >= NE) e = NE - 1;            // tail duplicate; out stores guarded
        int u = load_index(idx, 2LL * e, is64);
        int v = load_index(idx, 2LL * e + 1, is64);
        float du = g_deg[u], dv = g_deg[v];
        float su = (du > 1.f) ? 1.f / (du - 1.f) : 0.f;
        float sv = (dv > 1.f) ? 1.f / (dv - 1.f) : 0.f;
        int c0 = (tid & 1) * 8;             // float4 chunk base
        const float4* pe = reinterpret_cast<const float4*>(emb + (size_t)e * DIM);
        const float4* pu = reinterpret_cast<const float4*>(g_node_sum + (size_t)u * DIM);
        const float4* pv = reinterpret_cast<const float4*>(g_node_sum + (size_t)v * DIM);
        #pragma unroll
        for (int c = 0; c < 8; ++c) {
            int cc = c0 + c;
            float4 em = pe[cc], nu = pu[cc], nv = pv[cc];
            float4 au, av;
            au.x = tf32r((nu.x - em.x) * su); au.y = tf32r((nu.y - em.y) * su);
            au.z = tf32r((nu.z - em.z) * su); au.w = tf32r((nu.w - em.w) * su);
            av.x = tf32r((nv.x - em.x) * sv); av.y = tf32r((nv.y - em.y) * sv);
            av.z = tf32r((nv.z - em.z) * sv); av.w = tf32r((nv.w - em.w) * sv);
            *reinterpret_cast<float4*>(sAu + le * AST + cc * 4) = au;
            *reinterpret_cast<float4*>(sAv + le * AST + cc * 4) = av;
        }
    }
    __syncthreads();

    // Mainloop: warp tile = 32 edges x 32 cols, both GEMMs.
    // wid>>1 selects edge block (m0), wid&1 selects column half (nh).
    const int g  = lane >> 2;
    const int tg = lane & 3;
    const int m0 = (wid >> 1) * 32;
    const int nh = (wid & 1) * 32;

    float dU[2][4][4] = {};
    float dV[2][4][4] = {};

    #pragma unroll
    for (int k0 = 0; k0 < DIM; k0 += 8) {
        uint32_t aU[2][4], aV[2][4];
        #pragma unroll
        for (int mi = 0; mi < 2; ++mi) {
            const float* bu = sAu + (m0 + mi * 16) * AST + k0;
            const float* bv = sAv + (m0 + mi * 16) * AST + k0;
            aU[mi][0] = __float_as_uint(bu[g * AST + tg]);
            aU[mi][1] = __float_as_uint(bu[(g + 8) * AST + tg]);
            aU[mi][2] = __float_as_uint(bu[g * AST + tg + 4]);
            aU[mi][3] = __float_as_uint(bu[(g + 8) * AST + tg + 4]);
            aV[mi][0] = __float_as_uint(bv[g * AST + tg]);
            aV[mi][1] = __float_as_uint(bv[(g + 8) * AST + tg]);
            aV[mi][2] = __float_as_uint(bv[g * AST + tg + 4]);
            aV[mi][3] = __float_as_uint(bv[(g + 8) * AST + tg + 4]);
        }
        #pragma unroll
        for (int nj = 0; nj < 4; ++nj) {
            int n = nh + nj * 8 + g;
            uint32_t bF[2], bB[2];
            bF[0] = __float_as_uint(sWf[(k0 + tg) * WST + n]);
            bF[1] = __float_as_uint(sWf[(k0 + tg + 4) * WST + n]);
            bB[0] = __float_as_uint(sWb[(k0 + tg) * WST + n]);
            bB[1] = __float_as_uint(sWb[(k0 + tg + 4) * WST + n]);
            mma8(dU[0][nj], aU[0], bF);
            mma8(dU[1][nj], aU[1], bF);
            mma8(dV[0][nj], aV[0], bB);
            mma8(dV[1][nj], aV[1], bB);
        }
    }
    __syncthreads();       // all warps done reading A tiles

    // Scatter accumulators back to smem (reuse A tiles): af -> sAu, ab -> sAv
    #pragma unroll
    for (int mi = 0; mi < 2; ++mi) {
        #pragma unroll
        for (int nj = 0; nj < 4; ++nj) {
            int row = m0 + mi * 16 + g;
            int col = nh + nj * 8 + 2 * tg;
            *reinterpret_cast<float2*>(sAu + row * AST + col)
                = make_float2(dU[mi][nj][0], dU[mi][nj][1]);
            *reinterpret_cast<float2*>(sAu + (row + 8) * AST + col)
                = make_float2(dU[mi][nj][2], dU[mi][nj][3]);
            *reinterpret_cast<float2*>(sAv + row * AST + col)
                = make_float2(dV[mi][nj][0], dV[mi][nj][1]);
            *reinterpret_cast<float2*>(sAv + (row + 8) * AST + col)
                = make_float2(dV[mi][nj][2], dV[mi][nj][3]);
        }
    }
    __syncthreads();

    // Epilogue: 2 threads per edge; gate dot via shfl pair-sum, blend, store.
    {
        int le = tid >> 1;
        int ch = (tid & 1) * 32;
        const float4* pa  = reinterpret_cast<const float4*>(sAu + le * AST + ch);
        const float4* pb  = reinterpret_cast<const float4*>(sAv + le * AST + ch);
        const float4* pbf = reinterpret_cast<const float4*>(sBf + ch);
        const float4* pbb = reinterpret_cast<const float4*>(sBb + ch);
        const float4* pwg = reinterpret_cast<const float4*>(sWg + ch);

        float af[32], ab[32];
        float t = 0.f;
        #pragma unroll
        for (int q = 0; q < 8; ++q) {
            float4 a4 = pa[q], b4 = pb[q], f4 = pbf[q], s4 = pbb[q], w4 = pwg[q];
            af[q*4+0] = a4.x + f4.x;  ab[q*4+0] = b4.x + s4.x;
            af[q*4+1] = a4.y + f4.y;  ab[q*4+1] = b4.y + s4.y;
            af[q*4+2] = a4.z + f4.z;  ab[q*4+2] = b4.z + s4.z;
            af[q*4+3] = a4.w + f4.w;  ab[q*4+3] = b4.w + s4.w;
            t = fmaf(af[q*4+0] + ab[q*4+0], w4.x, t);
            t = fmaf(af[q*4+1] + ab[q*4+1], w4.y, t);
            t = fmaf(af[q*4+2] + ab[q*4+2], w4.z, t);
            t = fmaf(af[q*4+3] + ab[q*4+3], w4.w, t);
        }
        t += __shfl_xor_sync(0xffffffffu, t, 1);
        float gg = 1.f / (1.f + expf(-(t + __ldg(bg))));
        float gm = 1.f - gg;

        int eo = blockIdx.x * TM + le;
        if (eo < NE) {
            float4* po = reinterpret_cast<float4*>(out + (size_t)eo * DIM + ch);
            #pragma unroll
            for (int q = 0; q < 8; ++q) {
                float4 o;
                o.x = gg * af[q*4+0] + gm * ab[q*4+0];
                o.y = gg * af[q*4+1] + gm * ab[q*4+1];
                o.z = gg * af[q*4+2] + gm * ab[q*4+2];
                o.w = gg * af[q*4+3] + gm * ab[q*4+3];
                po[q] = o;
            }
        }
    }
}

extern "C" void kernel_launch(void* const* d_in, const int* in_sizes, int n_in,
                              void* d_out, int out_size) {
    const float* emb = (const float*)d_in[0];
    const float* Wf  = (const float*)d_in[1];
    const float* bf  = (const float*)d_in[2];
    const float* Wb  = (const float*)d_in[3];
    const float* bb  = (const float*)d_in[4];
    const float* Wg  = (const float*)d_in[5];
    const float* bg  = (const float*)d_in[6];
    const void*  idx = d_in[7];
    float* out = (float*)d_out;

    (void)in_sizes; (void)n_in; (void)out_size;

    detect_kernel<<<1, 256>>>((const int*)idx);

    int zthreads = (N_NODES * DIM) / 4;
    zero_kernel<<<(zthreads + 255) / 256, 256>>>();

    int sthreads = NE * 16;
    scatter_kernel<<<(sthreads + 255) / 256, 256>>>(emb, idx);

    int smem = (2 * TM * AST + 2 * DIM * WST + 3 * DIM) * (int)sizeof(float); // 107264
    cudaFuncSetAttribute(fused_kernel,
                         cudaFuncAttributeMaxDynamicSharedMemorySize, smem);
    int grid = (NE + TM - 1) / TM;   // 7813
    fused_kernel<<<grid, 256, smem>>>(emb, Wf, bf, Wb, bb, Wg, bg, idx, out);
}

// round 10
// speedup vs baseline: 1.0136x; 1.0136x over previous
#include <cuda_runtime.h>
#include <math.h>
#include <stdint.h>

#define N_NODES 100000
#define NE      1000000
#define DIM     64
#define TM      128          // edges per CTA in fused kernel
#define AST     68           // A tile row stride (floats): bank-conflict-free quads
#define WST     72           // W tile row stride (floats): conflict-free B-frag loads

// ---------------- scratch (allocation-free rule) ----------------
__device__ float g_node_sum[(size_t)N_NODES * DIM];   // 25.6 MB
__device__ float g_deg[N_NODES];
__device__ int   g_is64;
__device__ float g_wfg[DIM];     // Wf @ Wg
__device__ float g_wbg[DIM];     // Wb @ Wg
__device__ float g_cb;           // (bf+bb)@Wg + bg

// ---------------- dtype probe (proven round 3) ----------------
__global__ void detect_kernel(const int* __restrict__ idx32) {
    __shared__ int any_nonzero;
    if (threadIdx.x == 0) any_nonzero = 0;
    __syncthreads();
    int t = threadIdx.x;
    #pragma unroll
    for (int i = 0; i < 4; ++i) {
        int pos = 2 * (t + i * 256) + 1;
        if (idx32[pos] != 0) any_nonzero = 1;
    }
    __syncthreads();
    if (threadIdx.x == 0) g_is64 = any_nonzero ? 0 : 1;
}

__device__ __forceinline__ int load_index(const void* idx, long long pos, int is64) {
    long long r = is64 ? ((const long long*)idx)[pos]
                       : (long long)((const int*)idx)[pos];
    if (r < 0) r = 0;
    if (r >= N_NODES) r = N_NODES - 1;
    return (int)r;
}

__global__ void zero_kernel() {
    size_t i = (size_t)blockIdx.x * blockDim.x + threadIdx.x;
    float4 z = make_float4(0.f, 0.f, 0.f, 0.f);
    if (i < (size_t)N_NODES * DIM / 4)
        reinterpret_cast<float4*>(g_node_sum)[i] = z;
    if (i < N_NODES / 4)
        reinterpret_cast<float4*>(g_deg)[i] = z;
}

// Gate-vector precompute: wfg[k] = sum_n Wf[k][n]*Wg[n]; cb = (bf+bb)@Wg + bg
__global__ void gatevec_kernel(const float* __restrict__ Wf,
                               const float* __restrict__ Wb,
                               const float* __restrict__ bf,
                               const float* __restrict__ bb,
                               const float* __restrict__ Wg,
                               const float* __restrict__ bg) {
    int k = threadIdx.x;          // 64 threads
    float sf = 0.f, sb = 0.f;
    #pragma unroll 8
    for (int n = 0; n < DIM; ++n) {
        float w = Wg[n];
        sf = fmaf(Wf[k * DIM + n], w, sf);
        sb = fmaf(Wb[k * DIM + n], w, sb);
    }
    g_wfg[k] = sf;
    g_wbg[k] = sb;
    if (k == 0) {
        float c = 0.f;
        for (int n = 0; n < DIM; ++n) c = fmaf(bf[n] + bb[n], Wg[n], c);
        g_cb = c + bg[0];
    }
}

// ---------------- scatter (proven round 3) ----------------
__global__ void scatter_kernel(const float* __restrict__ emb,
                               const void* __restrict__ idx) {
    const int is64 = g_is64;
    int t = blockIdx.x * blockDim.x + threadIdx.x;
    int e = t >> 4;
    if (e >= NE) return;
    int q = t & 15;
    int u = load_index(idx, 2LL * e, is64);
    int v = load_index(idx, 2LL * e + 1, is64);
    float4 val = reinterpret_cast<const float4*>(emb)[e * 16 + q];
    float* pu = g_node_sum + (size_t)u * DIM + q * 4;
    float* pv = g_node_sum + (size_t)v * DIM + q * 4;
    asm volatile("red.global.add.v4.f32 [%0], {%1, %2, %3, %4};"
                 :: "l"(pu), "f"(val.x), "f"(val.y), "f"(val.z), "f"(val.w)
                 : "memory");
    asm volatile("red.global.add.v4.f32 [%0], {%1, %2, %3, %4};"
                 :: "l"(pv), "f"(val.x), "f"(val.y), "f"(val.z), "f"(val.w)
                 : "memory");
    if (q == 0) {
        atomicAdd(&g_deg[u], 1.0f);
        atomicAdd(&g_deg[v], 1.0f);
    }
}

// ---------------- mma.sync tf32 helpers (target-neutral PTX) ----------------
__device__ __forceinline__ float tf32r(float x) {
    uint32_t u;
    asm("cvt.rna.tf32.f32 %0, %1;" : "=r"(u) : "f"(x));
    return __uint_as_float(u);
}
__device__ __forceinline__ void mma8(float* d, const uint32_t* a, const uint32_t* b) {
    asm volatile(
        "mma.sync.aligned.m16n8k8.row.col.f32.tf32.tf32.f32 "
        "{%0,%1,%2,%3}, {%4,%5,%6,%7}, {%8,%9}, {%0,%1,%2,%3};"
        : "+f"(d[0]), "+f"(d[1]), "+f"(d[2]), "+f"(d[3])
        : "r"(a[0]), "r"(a[1]), "r"(a[2]), "r"(a[3]), "r"(b[0]), "r"(b[1]));
}

// ---------------- fused kernel: tf32 dual GEMM, gate-in-gather ----------------
// smem floats: sAu[128][AST], sAv[128][AST], sWf[64][WST], sWb[64][WST],
//              sBf[64], sBb[64], sG[128]  => 26880 floats = 107520 B
__global__ __launch_bounds__(256, 2)
void fused_kernel(const float* __restrict__ emb,
                  const float* __restrict__ Wf, const float* __restrict__ bf,
                  const float* __restrict__ Wb, const float* __restrict__ bb,
                  const float* __restrict__ Wg, const float* __restrict__ bg,
                  const void* __restrict__ idx,
                  float* __restrict__ out) {
    extern __shared__ float sm[];
    float* sAu = sm;
    float* sAv = sAu + TM * AST;
    float* sWf = sAv + TM * AST;
    float* sWb = sWf + DIM * WST;
    float* sBf = sWb + DIM * WST;
    float* sBb = sBf + DIM;
    float* sG  = sBb + DIM;

    const int tid  = threadIdx.x;
    const int lane = tid & 31;
    const int wid  = tid >> 5;
    const int is64 = g_is64;

    // Stage weights (tf32-rounded) + biases
    #pragma unroll
    for (int i = 0; i < 16; ++i) {
        int lin = tid + i * 256;
        int k = lin >> 6, n = lin & 63;
        sWf[k * WST + n] = tf32r(Wf[lin]);
        sWb[k * WST + n] = tf32r(Wb[lin]);
    }
    if (tid < DIM) {
        sBf[tid] = bf[tid];
        sBb[tid] = bb[tid];
    }

    // Build A tiles + per-edge gate (2 threads per edge, 32 dims each).
    {
        int le = tid >> 1;
        int e  = blockIdx.x * TM + le;
        if (e >= NE) e = NE - 1;            // tail duplicate; stores guarded
        int u = load_index(idx, 2LL * e, is64);
        int v = load_index(idx, 2LL * e + 1, is64);
        float du = g_deg[u], dv = g_deg[v];
        float su = (du > 1.f) ? 1.f / (du - 1.f) : 0.f;
        float sv = (dv > 1.f) ? 1.f / (dv - 1.f) : 0.f;
        int c0 = (tid & 1) * 8;
        const float4* pe = reinterpret_cast<const float4*>(emb + (size_t)e * DIM);
        const float4* pu = reinterpret_cast<const float4*>(g_node_sum + (size_t)u * DIM);
        const float4* pv = reinterpret_cast<const float4*>(g_node_sum + (size_t)v * DIM);
        const float4* pwf = reinterpret_cast<const float4*>(g_wfg);
        const float4* pwb = reinterpret_cast<const float4*>(g_wbg);
        float t = 0.f;
        #pragma unroll
        for (int c = 0; c < 8; ++c) {
            int cc = c0 + c;
            float4 em = pe[cc], nu = pu[cc], nv = pv[cc];
            float4 wf4 = pwf[cc], wb4 = pwb[cc];
            float4 au, av;
            au.x = (nu.x - em.x) * su; au.y = (nu.y - em.y) * su;
            au.z = (nu.z - em.z) * su; au.w = (nu.w - em.w) * su;
            av.x = (nv.x - em.x) * sv; av.y = (nv.y - em.y) * sv;
            av.z = (nv.z - em.z) * sv; av.w = (nv.w - em.w) * sv;
            t = fmaf(au.x, wf4.x, t); t = fmaf(au.y, wf4.y, t);
            t = fmaf(au.z, wf4.z, t); t = fmaf(au.w, wf4.w, t);
            t = fmaf(av.x, wb4.x, t); t = fmaf(av.y, wb4.y, t);
            t = fmaf(av.z, wb4.z, t); t = fmaf(av.w, wb4.w, t);
            float4 auq = make_float4(tf32r(au.x), tf32r(au.y), tf32r(au.z), tf32r(au.w));
            float4 avq = make_float4(tf32r(av.x), tf32r(av.y), tf32r(av.z), tf32r(av.w));
            *reinterpret_cast<float4*>(sAu + le * AST + cc * 4) = auq;
            *reinterpret_cast<float4*>(sAv + le * AST + cc * 4) = avq;
        }
        t += __shfl_xor_sync(0xffffffffu, t, 1);
        float gg = 1.f / (1.f + expf(-(t + g_cb)));
        if ((tid & 1) == 0) sG[le] = gg;
    }
    __syncthreads();        // the ONLY barrier

    // Mainloop: warp tile = 32 edges x 32 cols, both GEMMs.
    const int g  = lane >> 2;
    const int tg = lane & 3;
    const int m0 = (wid >> 1) * 32;
    const int nh = (wid & 1) * 32;

    float dU[2][4][4] = {};
    float dV[2][4][4] = {};

    #pragma unroll
    for (int k0 = 0; k0 < DIM; k0 += 8) {
        uint32_t aU[2][4], aV[2][4];
        #pragma unroll
        for (int mi = 0; mi < 2; ++mi) {
            const float* bu = sAu + (m0 + mi * 16) * AST + k0;
            const float* bv = sAv + (m0 + mi * 16) * AST + k0;
            aU[mi][0] = __float_as_uint(bu[g * AST + tg]);
            aU[mi][1] = __float_as_uint(bu[(g + 8) * AST + tg]);
            aU[mi][2] = __float_as_uint(bu[g * AST + tg + 4]);
            aU[mi][3] = __float_as_uint(bu[(g + 8) * AST + tg + 4]);
            aV[mi][0] = __float_as_uint(bv[g * AST + tg]);
            aV[mi][1] = __float_as_uint(bv[(g + 8) * AST + tg]);
            aV[mi][2] = __float_as_uint(bv[g * AST + tg + 4]);
            aV[mi][3] = __float_as_uint(bv[(g + 8) * AST + tg + 4]);
        }
        #pragma unroll
        for (int nj = 0; nj < 4; ++nj) {
            int n = nh + nj * 8 + g;
            uint32_t bF[2], bB[2];
            bF[0] = __float_as_uint(sWf[(k0 + tg) * WST + n]);
            bF[1] = __float_as_uint(sWf[(k0 + tg + 4) * WST + n]);
            bB[0] = __float_as_uint(sWb[(k0 + tg) * WST + n]);
            bB[1] = __float_as_uint(sWb[(k0 + tg + 4) * WST + n]);
            mma8(dU[0][nj], aU[0], bF);
            mma8(dU[1][nj], aU[1], bF);
            mma8(dV[0][nj], aV[0], bB);
            mma8(dV[1][nj], aV[1], bB);
        }
    }

    // Epilogue directly from fragments: out = g*(dU+bf) + (1-g)*(dV+bb)
    const int ebase = blockIdx.x * TM;
    #pragma unroll
    for (int mi = 0; mi < 2; ++mi) {
        int r0 = m0 + mi * 16 + g;
        float g0 = sG[r0], g1 = sG[r0 + 8];
        float h0 = 1.f - g0, h1 = 1.f - g1;
        bool v0 = (ebase + r0) < NE;
        bool v1 = (ebase + r0 + 8) < NE;
        #pragma unroll
        for (int nj = 0; nj < 4; ++nj) {
            int col = nh + nj * 8 + 2 * tg;
            float bf0 = sBf[col], bf1 = sBf[col + 1];
            float bb0 = sBb[col], bb1 = sBb[col + 1];
            if (v0) {
                float2 o;
                o.x = g0 * (dU[mi][nj][0] + bf0) + h0 * (dV[mi][nj][0] + bb0);
                o.y = g0 * (dU[mi][nj][1] + bf1) + h0 * (dV[mi][nj][1] + bb1);
                *reinterpret_cast<float2*>(out + (size_t)(ebase + r0) * DIM + col) = o;
            }
            if (v1) {
                float2 o;
                o.x = g1 * (dU[mi][nj][2] + bf0) + h1 * (dV[mi][nj][2] + bb0);
                o.y = g1 * (dU[mi][nj][3] + bf1) + h1 * (dV[mi][nj][3] + bb1);
                *reinterpret_cast<float2*>(out + (size_t)(ebase + r0 + 8) * DIM + col) = o;
            }
        }
    }
}

extern "C" void kernel_launch(void* const* d_in, const int* in_sizes, int n_in,
                              void* d_out, int out_size) {
    const float* emb = (const float*)d_in[0];
    const float* Wf  = (const float*)d_in[1];
    const float* bf  = (const float*)d_in[2];
    const float* Wb  = (const float*)d_in[3];
    const float* bb  = (const float*)d_in[4];
    const float* Wg  = (const float*)d_in[5];
    const float* bg  = (const float*)d_in[6];
    const void*  idx = d_in[7];
    float* out = (float*)d_out;

    (void)in_sizes; (void)n_in; (void)out_size;

    detect_kernel<<<1, 256>>>((const int*)idx);

    int zthreads = (N_NODES * DIM) / 4;
    zero_kernel<<<(zthreads + 255) / 256, 256>>>();

    gatevec_kernel<<<1, 64>>>(Wf, Wb, bf, bb, Wg, bg);

    int sthreads = NE * 16;
    scatter_kernel<<<(sthreads + 255) / 256, 256>>>(emb, idx);

    int smem = (2 * TM * AST + 2 * DIM * WST + 2 * DIM + TM) * (int)sizeof(float); // 107520
    cudaFuncSetAttribute(fused_kernel,
                         cudaFuncAttributeMaxDynamicSharedMemorySize, smem);
    int grid = (NE + TM - 1) / TM;   // 7813
    fused_kernel<<<grid, 256, smem>>>(emb, Wf, bf, Wb, bb, Wg, bg, idx, out);
}

// round 11
// speedup vs baseline: 1.3510x; 1.3329x over previous
#include <cuda_runtime.h>
#include <math.h>
#include <stdint.h>

#define N_NODES 100000
#define NE      1000000
#define DIM     64
#define TM      64           // edges per CTA in fused kernel
#define AST     68           // A tile row stride (floats): conflict-free

// ---------------- scratch (allocation-free rule) ----------------
__device__ float g_node_sum[(size_t)N_NODES * DIM];   // 25.6 MB
__device__ float g_deg[N_NODES];
__device__ int   g_is64;
__device__ float g_wfg[DIM];              // Wf @ Wg
__device__ float g_wbg[DIM];              // Wb @ Wg
__device__ float g_cb;                    // (bf+bb)@Wg + bg
__device__ float g_wfragF[2 * 8 * 32 * 8];  // fragment-ordered tf32 Wf
__device__ float g_wfragB[2 * 8 * 32 * 8];  // fragment-ordered tf32 Wb

// ---------------- dtype probe (proven round 3) ----------------
__global__ void detect_kernel(const int* __restrict__ idx32) {
    __shared__ int any_nonzero;
    if (threadIdx.x == 0) any_nonzero = 0;
    __syncthreads();
    int t = threadIdx.x;
    #pragma unroll
    for (int i = 0; i < 4; ++i) {
        int pos = 2 * (t + i * 256) + 1;
        if (idx32[pos] != 0) any_nonzero = 1;
    }
    __syncthreads();
    if (threadIdx.x == 0) g_is64 = any_nonzero ? 0 : 1;
}

__device__ __forceinline__ int load_index(const void* idx, long long pos, int is64) {
    long long r = is64 ? ((const long long*)idx)[pos]
                       : (long long)((const int*)idx)[pos];
    if (r < 0) r = 0;
    if (r >= N_NODES) r = N_NODES - 1;
    return (int)r;
}

__global__ void zero_kernel() {
    size_t i = (size_t)blockIdx.x * blockDim.x + threadIdx.x;
    float4 z = make_float4(0.f, 0.f, 0.f, 0.f);
    if (i < (size_t)N_NODES * DIM / 4)
        reinterpret_cast<float4*>(g_node_sum)[i] = z;
    if (i < N_NODES / 4)
        reinterpret_cast<float4*>(g_deg)[i] = z;
}

__device__ __forceinline__ float tf32r(float x) {
    uint32_t u;
    asm("cvt.rna.tf32.f32 %0, %1;" : "=r"(u) : "f"(x));
    return __uint_as_float(u);
}

// Prep: gate vectors + fragment-ordered tf32 weight arrays.
// frag linear index: ((nh*8 + k0)*32 + lane)*8 + (nj*2 + p)
//   value = W[(k0*8 + tg + p*4)*64 + (nh*32 + nj*8 + g)],  tg=lane&3, g=lane>>2
__global__ void prep_kernel(const float* __restrict__ Wf,
                            const float* __restrict__ Wb,
                            const float* __restrict__ bf,
                            const float* __restrict__ bb,
                            const float* __restrict__ Wg,
                            const float* __restrict__ bg) {
    int tid = threadIdx.x;                // 256
    if (tid < DIM) {
        float w, sf = 0.f, sb = 0.f;
        #pragma unroll 8
        for (int n = 0; n < DIM; ++n) {
            w = Wg[n];
            sf = fmaf(Wf[tid * DIM + n], w, sf);
            sb = fmaf(Wb[tid * DIM + n], w, sb);
        }
        g_wfg[tid] = sf;
        g_wbg[tid] = sb;
        if (tid == 0) {
            float c = 0.f;
            for (int n = 0; n < DIM; ++n) c = fmaf(bf[n] + bb[n], Wg[n], c);
            g_cb = c + bg[0];
        }
    }
    #pragma unroll
    for (int i = 0; i < 16; ++i) {
        int lin  = tid + i * 256;         // 0..4095
        int j    = lin & 7;
        int lane = (lin >> 3) & 31;
        int k0   = (lin >> 8) & 7;
        int nh   = lin >> 11;
        int tg = lane & 3, g = lane >> 2;
        int p = j & 1, nj = j >> 1;
        int k = k0 * 8 + tg + p * 4;
        int n = nh * 32 + nj * 8 + g;
        g_wfragF[lin] = tf32r(Wf[k * DIM + n]);
        g_wfragB[lin] = tf32r(Wb[k * DIM + n]);
    }
}

// ---------------- scatter (proven round 3) ----------------
__global__ void scatter_kernel(const float* __restrict__ emb,
                               const void* __restrict__ idx) {
    const int is64 = g_is64;
    int t = blockIdx.x * blockDim.x + threadIdx.x;
    int e = t >> 4;
    if (e >= NE) return;
    int q = t & 15;
    int u = load_index(idx, 2LL * e, is64);
    int v = load_index(idx, 2LL * e + 1, is64);
    float4 val = reinterpret_cast<const float4*>(emb)[e * 16 + q];
    float* pu = g_node_sum + (size_t)u * DIM + q * 4;
    float* pv = g_node_sum + (size_t)v * DIM + q * 4;
    asm volatile("red.global.add.v4.f32 [%0], {%1, %2, %3, %4};"
                 :: "l"(pu), "f"(val.x), "f"(val.y), "f"(val.z), "f"(val.w)
                 : "memory");
    asm volatile("red.global.add.v4.f32 [%0], {%1, %2, %3, %4};"
                 :: "l"(pv), "f"(val.x), "f"(val.y), "f"(val.z), "f"(val.w)
                 : "memory");
    if (q == 0) {
        atomicAdd(&g_deg[u], 1.0f);
        atomicAdd(&g_deg[v], 1.0f);
    }
}

// ---------------- mma helpers ----------------
__device__ __forceinline__ void mma8(float* d, const uint32_t* a, const uint32_t* b) {
    asm volatile(
        "mma.sync.aligned.m16n8k8.row.col.f32.tf32.tf32.f32 "
        "{%0,%1,%2,%3}, {%4,%5,%6,%7}, {%8,%9}, {%0,%1,%2,%3};"
        : "+f"(d[0]), "+f"(d[1]), "+f"(d[2]), "+f"(d[3])
        : "r"(a[0]), "r"(a[1]), "r"(a[2]), "r"(a[3]), "r"(b[0]), "r"(b[1]));
}
__device__ __forceinline__ void ldm4(uint32_t* r, uint32_t addr) {
    asm volatile("ldmatrix.sync.aligned.m8n8.x4.shared.b16 {%0,%1,%2,%3}, [%4];"
                 : "=r"(r[0]), "=r"(r[1]), "=r"(r[2]), "=r"(r[3]) : "r"(addr));
}
__device__ __forceinline__ uint32_t smem_u32(const void* p) {
    uint32_t a;
    asm("{ .reg .u64 t; cvta.to.shared.u64 t, %1; cvt.u32.u64 %0, t; }" : "=r"(a) : "l"(p));
    return a;
}

// ---------------- fused kernel: 64 edges/CTA, 128 thr, 5 CTAs/SM ----------------
// smem floats: sAu[64][AST], sAv[64][AST], sBf[64], sBb[64], sG[64] = 35584 B
__global__ __launch_bounds__(128, 5)
void fused_kernel(const float* __restrict__ emb,
                  const float* __restrict__ bf, const float* __restrict__ bb,
                  const void* __restrict__ idx,
                  float* __restrict__ out) {
    extern __shared__ float sm[];
    float* sAu = sm;
    float* sAv = sAu + TM * AST;
    float* sBf = sAv + TM * AST;
    float* sBb = sBf + DIM;
    float* sG  = sBb + DIM;

    const int tid  = threadIdx.x;
    const int lane = tid & 31;
    const int wid  = tid >> 5;
    const int is64 = g_is64;

    if (tid < DIM) {
        sBf[tid] = bf[tid];
        sBb[tid] = bb[tid];
    }

    // Build A tiles + per-edge gate (2 threads per edge, 32 dims each)
    {
        int le = tid >> 1;                 // 0..63
        int e  = blockIdx.x * TM + le;     // grid exact: e < NE always
        int u = load_index(idx, 2LL * e, is64);
        int v = load_index(idx, 2LL * e + 1, is64);
        float du = g_deg[u], dv = g_deg[v];
        float su = (du > 1.f) ? 1.f / (du - 1.f) : 0.f;
        float sv = (dv > 1.f) ? 1.f / (dv - 1.f) : 0.f;
        int c0 = (tid & 1) * 8;
        const float4* pe = reinterpret_cast<const float4*>(emb + (size_t)e * DIM);
        const float4* pu = reinterpret_cast<const float4*>(g_node_sum + (size_t)u * DIM);
        const float4* pv = reinterpret_cast<const float4*>(g_node_sum + (size_t)v * DIM);
        const float4* pwf = reinterpret_cast<const float4*>(g_wfg);
        const float4* pwb = reinterpret_cast<const float4*>(g_wbg);
        float t = 0.f;
        #pragma unroll
        for (int c = 0; c < 8; ++c) {
            int cc = c0 + c;
            float4 em = pe[cc], nu = pu[cc], nv = pv[cc];
            float4 wf4 = pwf[cc], wb4 = pwb[cc];
            float4 au, av;
            au.x = (nu.x - em.x) * su; au.y = (nu.y - em.y) * su;
            au.z = (nu.z - em.z) * su; au.w = (nu.w - em.w) * su;
            av.x = (nv.x - em.x) * sv; av.y = (nv.y - em.y) * sv;
            av.z = (nv.z - em.z) * sv; av.w = (nv.w - em.w) * sv;
            t = fmaf(au.x, wf4.x, t); t = fmaf(au.y, wf4.y, t);
            t = fmaf(au.z, wf4.z, t); t = fmaf(au.w, wf4.w, t);
            t = fmaf(av.x, wb4.x, t); t = fmaf(av.y, wb4.y, t);
            t = fmaf(av.z, wb4.z, t); t = fmaf(av.w, wb4.w, t);
            float4 auq = make_float4(tf32r(au.x), tf32r(au.y), tf32r(au.z), tf32r(au.w));
            float4 avq = make_float4(tf32r(av.x), tf32r(av.y), tf32r(av.z), tf32r(av.w));
            *reinterpret_cast<float4*>(sAu + le * AST + cc * 4) = auq;
            *reinterpret_cast<float4*>(sAv + le * AST + cc * 4) = avq;
        }
        t += __shfl_xor_sync(0xffffffffu, t, 1);
        float gg = 1.f / (1.f + expf(-(t + g_cb)));
        if ((tid & 1) == 0) sG[le] = gg;
    }
    __syncthreads();        // the only barrier

    // Mainloop: warp tile 32 edges x 32 cols, both GEMMs.
    const int g  = lane >> 2;
    const int tg = lane & 3;
    const int m0 = (wid >> 1) * 32;
    const int nh = wid & 1;

    // ldmatrix lane->row mapping: row = lane&15, col-half = lane>>4 (4 floats)
    const int lrow  = lane & 15;
    const int lkoff = (lane >> 4) * 4;
    uint32_t aaddrU0 = smem_u32(sAu + (m0 + lrow) * AST + lkoff);
    uint32_t aaddrU1 = smem_u32(sAu + (m0 + 16 + lrow) * AST + lkoff);
    uint32_t aaddrV0 = smem_u32(sAv + (m0 + lrow) * AST + lkoff);
    uint32_t aaddrV1 = smem_u32(sAv + (m0 + 16 + lrow) * AST + lkoff);

    const float4* pF = reinterpret_cast<const float4*>(g_wfragF) + (nh * 8 * 32 + lane) * 2;
    const float4* pB = reinterpret_cast<const float4*>(g_wfragB) + (nh * 8 * 32 + lane) * 2;

    float dU[2][4][4] = {};
    float dV[2][4][4] = {};

    #pragma unroll
    for (int k0 = 0; k0 < 8; ++k0) {
        uint32_t aU[2][4], aV[2][4];
        ldm4(aU[0], aaddrU0 + k0 * 32);
        ldm4(aU[1], aaddrU1 + k0 * 32);
        ldm4(aV[0], aaddrV0 + k0 * 32);
        ldm4(aV[1], aaddrV1 + k0 * 32);

        float4 f0 = pF[k0 * 64 + 0], f1 = pF[k0 * 64 + 1];
        float4 b0 = pB[k0 * 64 + 0], b1 = pB[k0 * 64 + 1];
        uint32_t bF[4][2] = {
            {__float_as_uint(f0.x), __float_as_uint(f0.y)},
            {__float_as_uint(f0.z), __float_as_uint(f0.w)},
            {__float_as_uint(f1.x), __float_as_uint(f1.y)},
            {__float_as_uint(f1.z), __float_as_uint(f1.w)}};
        uint32_t bB[4][2] = {
            {__float_as_uint(b0.x), __float_as_uint(b0.y)},
            {__float_as_uint(b0.z), __float_as_uint(b0.w)},
            {__float_as_uint(b1.x), __float_as_uint(b1.y)},
            {__float_as_uint(b1.z), __float_as_uint(b1.w)}};

        #pragma unroll
        for (int nj = 0; nj < 4; ++nj) {
            mma8(dU[0][nj], aU[0], bF[nj]);
            mma8(dU[1][nj], aU[1], bF[nj]);
            mma8(dV[0][nj], aV[0], bB[nj]);
            mma8(dV[1][nj], aV[1], bB[nj]);
        }
    }

    // Epilogue directly from fragments: out = g*(dU+bf) + (1-g)*(dV+bb)
    const int ebase = blockIdx.x * TM;
    #pragma unroll
    for (int mi = 0; mi < 2; ++mi) {
        int r0 = m0 + mi * 16 + g;
        float g0 = sG[r0], g1 = sG[r0 + 8];
        float h0 = 1.f - g0, h1 = 1.f - g1;
        #pragma unroll
        for (int nj = 0; nj < 4; ++nj) {
            int col = nh * 32 + nj * 8 + 2 * tg;
            float bf0 = sBf[col], bf1 = sBf[col + 1];
            float bb0 = sBb[col], bb1 = sBb[col + 1];
            float2 o;
            o.x = g0 * (dU[mi][nj][0] + bf0) + h0 * (dV[mi][nj][0] + bb0);
            o.y = g0 * (dU[mi][nj][1] + bf1) + h0 * (dV[mi][nj][1] + bb1);
            *reinterpret_cast<float2*>(out + (size_t)(ebase + r0) * DIM + col) = o;
            o.x = g1 * (dU[mi][nj][2] + bf0) + h1 * (dV[mi][nj][2] + bb0);
            o.y = g1 * (dU[mi][nj][3] + bf1) + h1 * (dV[mi][nj][3] + bb1);
            *reinterpret_cast<float2*>(out + (size_t)(ebase + r0 + 8) * DIM + col) = o;
        }
    }
}

extern "C" void kernel_launch(void* const* d_in, const int* in_sizes, int n_in,
                              void* d_out, int out_size) {
    const float* emb = (const float*)d_in[0];
    const float* Wf  = (const float*)d_in[1];
    const float* bf  = (const float*)d_in[2];
    const float* Wb  = (const float*)d_in[3];
    const float* bb  = (const float*)d_in[4];
    const float* Wg  = (const float*)d_in[5];
    const float* bg  = (const float*)d_in[6];
    const void*  idx = d_in[7];
    float* out = (float*)d_out;

    (void)in_sizes; (void)n_in; (void)out_size;

    detect_kernel<<<1, 256>>>((const int*)idx);

    int zthreads = (N_NODES * DIM) / 4;
    zero_kernel<<<(zthreads + 255) / 256, 256>>>();

    prep_kernel<<<1, 256>>>(Wf, Wb, bf, bb, Wg, bg);

    int sthreads = NE * 16;
    scatter_kernel<<<(sthreads + 255) / 256, 256>>>(emb, idx);

    int smem = (2 * TM * AST + 2 * DIM + TM) * (int)sizeof(float);   // 35584
    cudaFuncSetAttribute(fused_kernel,
                         cudaFuncAttributeMaxDynamicSharedMemorySize, smem);
    fused_kernel<<<NE / TM, 128, smem>>>(emb, bf, bb, idx, out);
}

// round 12
// speedup vs baseline: 1.8961x; 1.4035x over previous
#include <cuda_runtime.h>
#include <math.h>
#include <stdint.h>

#define N_NODES 100000
#define NE      1000000
#define DIM     64
#define TM      64           // edges per CTA in fused kernel
#define AST     68           // A tile row stride (floats): conflict-free

// ---------------- scratch (allocation-free rule) ----------------
__device__ float g_node_sum[(size_t)N_NODES * DIM];   // 25.6 MB
__device__ float g_deg[N_NODES];
__device__ int   g_is64;
__device__ float g_wfg[DIM];              // Wf @ Wg
__device__ float g_wbg[DIM];              // Wb @ Wg
__device__ float g_cb;                    // (bf+bb)@Wg + bg
__device__ float g_wfragF[2 * 8 * 32 * 8];  // fragment-ordered tf32 Wf
__device__ float g_wfragB[2 * 8 * 32 * 8];  // fragment-ordered tf32 Wb

// ---------------- dtype probe (proven round 3) ----------------
__global__ void detect_kernel(const int* __restrict__ idx32) {
    __shared__ int any_nonzero;
    if (threadIdx.x == 0) any_nonzero = 0;
    __syncthreads();
    int t = threadIdx.x;
    #pragma unroll
    for (int i = 0; i < 4; ++i) {
        int pos = 2 * (t + i * 256) + 1;
        if (idx32[pos] != 0) any_nonzero = 1;
    }
    __syncthreads();
    if (threadIdx.x == 0) g_is64 = any_nonzero ? 0 : 1;
}

__device__ __forceinline__ int load_index(const void* idx, long long pos, int is64) {
    long long r = is64 ? ((const long long*)idx)[pos]
                       : (long long)((const int*)idx)[pos];
    if (r < 0) r = 0;
    if (r >= N_NODES) r = N_NODES - 1;
    return (int)r;
}

__global__ void zero_kernel() {
    size_t i = (size_t)blockIdx.x * blockDim.x + threadIdx.x;
    float4 z = make_float4(0.f, 0.f, 0.f, 0.f);
    if (i < (size_t)N_NODES * DIM / 4)
        reinterpret_cast<float4*>(g_node_sum)[i] = z;
    if (i < N_NODES / 4)
        reinterpret_cast<float4*>(g_deg)[i] = z;
}

__device__ __forceinline__ float tf32r(float x) {
    uint32_t u;
    asm("cvt.rna.tf32.f32 %0, %1;" : "=r"(u) : "f"(x));
    return __uint_as_float(u);
}

// Prep: gate vectors + fragment-ordered tf32 weight arrays.
// frag linear index: ((nh*8 + k0)*32 + lane)*8 + (nj*2 + p)
//   value = W[(k0*8 + tg + p*4)*64 + (nh*32 + nj*8 + g)],  tg=lane&3, g=lane>>2
__global__ void prep_kernel(const float* __restrict__ Wf,
                            const float* __restrict__ Wb,
                            const float* __restrict__ bf,
                            const float* __restrict__ bb,
                            const float* __restrict__ Wg,
                            const float* __restrict__ bg) {
    int tid = threadIdx.x;                // 256
    if (tid < DIM) {
        float w, sf = 0.f, sb = 0.f;
        #pragma unroll 8
        for (int n = 0; n < DIM; ++n) {
            w = Wg[n];
            sf = fmaf(Wf[tid * DIM + n], w, sf);
            sb = fmaf(Wb[tid * DIM + n], w, sb);
        }
        g_wfg[tid] = sf;
        g_wbg[tid] = sb;
        if (tid == 0) {
            float c = 0.f;
            for (int n = 0; n < DIM; ++n) c = fmaf(bf[n] + bb[n], Wg[n], c);
            g_cb = c + bg[0];
        }
    }
    #pragma unroll
    for (int i = 0; i < 16; ++i) {
        int lin  = tid + i * 256;         // 0..4095
        int j    = lin & 7;
        int lane = (lin >> 3) & 31;
        int k0   = (lin >> 8) & 7;
        int nh   = lin >> 11;
        int tg = lane & 3, g = lane >> 2;
        int p = j & 1, nj = j >> 1;
        int k = k0 * 8 + tg + p * 4;
        int n = nh * 32 + nj * 8 + g;
        g_wfragF[lin] = tf32r(Wf[k * DIM + n]);
        g_wfragB[lin] = tf32r(Wb[k * DIM + n]);
    }
}

// ---------------- scatter (proven round 3) ----------------
__global__ void scatter_kernel(const float* __restrict__ emb,
                               const void* __restrict__ idx) {
    const int is64 = g_is64;
    int t = blockIdx.x * blockDim.x + threadIdx.x;
    int e = t >> 4;
    if (e >= NE) return;
    int q = t & 15;
    int u = load_index(idx, 2LL * e, is64);
    int v = load_index(idx, 2LL * e + 1, is64);
    float4 val = reinterpret_cast<const float4*>(emb)[e * 16 + q];
    float* pu = g_node_sum + (size_t)u * DIM + q * 4;
    float* pv = g_node_sum + (size_t)v * DIM + q * 4;
    asm volatile("red.global.add.v4.f32 [%0], {%1, %2, %3, %4};"
                 :: "l"(pu), "f"(val.x), "f"(val.y), "f"(val.z), "f"(val.w)
                 : "memory");
    asm volatile("red.global.add.v4.f32 [%0], {%1, %2, %3, %4};"
                 :: "l"(pv), "f"(val.x), "f"(val.y), "f"(val.z), "f"(val.w)
                 : "memory");
    if (q == 0) {
        atomicAdd(&g_deg[u], 1.0f);
        atomicAdd(&g_deg[v], 1.0f);
    }
}

// ---------------- mma helpers ----------------
__device__ __forceinline__ void mma8(float* d, const uint32_t* a, const uint32_t* b) {
    asm volatile(
        "mma.sync.aligned.m16n8k8.row.col.f32.tf32.tf32.f32 "
        "{%0,%1,%2,%3}, {%4,%5,%6,%7}, {%8,%9}, {%0,%1,%2,%3};"
        : "+f"(d[0]), "+f"(d[1]), "+f"(d[2]), "+f"(d[3])
        : "r"(a[0]), "r"(a[1]), "r"(a[2]), "r"(a[3]), "r"(b[0]), "r"(b[1]));
}
__device__ __forceinline__ void ldm4(uint32_t* r, uint32_t addr) {
    asm volatile("ldmatrix.sync.aligned.m8n8.x4.shared.b16 {%0,%1,%2,%3}, [%4];"
                 : "=r"(r[0]), "=r"(r[1]), "=r"(r[2]), "=r"(r[3]) : "r"(addr));
}
__device__ __forceinline__ uint32_t smem_u32(const void* p) {
    uint32_t a;
    asm("{ .reg .u64 t; cvta.to.shared.u64 t, %1; cvt.u32.u64 %0, t; }" : "=r"(a) : "l"(p));
    return a;
}

// ---------------- fused kernel: 64 edges/CTA, 128 thr, 5 CTAs/SM ----------------
// smem floats: sAu[64][AST], sAv[64][AST], sBf[64], sBb[64], sG[64] = 35584 B
__global__ __launch_bounds__(128, 5)
void fused_kernel(const float* __restrict__ emb,
                  const float* __restrict__ bf, const float* __restrict__ bb,
                  const void* __restrict__ idx,
                  float* __restrict__ out) {
    extern __shared__ float sm[];
    float* sAu = sm;
    float* sAv = sAu + TM * AST;
    float* sBf = sAv + TM * AST;
    float* sBb = sBf + DIM;
    float* sG  = sBb + DIM;

    const int tid  = threadIdx.x;
    const int lane = tid & 31;
    const int wid  = tid >> 5;
    const int is64 = g_is64;

    if (tid < DIM) {
        sBf[tid] = bf[tid];
        sBb[tid] = bb[tid];
    }

    // Build A tiles + per-edge gate. QUAD-PER-EDGE layout for coalescing:
    // 4 threads per edge (quad member m reads chunk i*4+m => 4 lanes cover
    // 64B contiguous per instruction => ~8 L1 wavefronts/instr instead of ~32).
    // Two passes of 32 edges.
    const int m  = tid & 3;
    #pragma unroll
    for (int pass = 0; pass < 2; ++pass) {
        int le = pass * 32 + (tid >> 2);   // 0..63
        int e  = blockIdx.x * TM + le;     // grid exact: e < NE always
        int u = load_index(idx, 2LL * e, is64);
        int v = load_index(idx, 2LL * e + 1, is64);
        float du = g_deg[u], dv = g_deg[v];
        float su = (du > 1.f) ? 1.f / (du - 1.f) : 0.f;
        float sv = (dv > 1.f) ? 1.f / (dv - 1.f) : 0.f;
        const float4* pe = reinterpret_cast<const float4*>(emb + (size_t)e * DIM);
        const float4* pu = reinterpret_cast<const float4*>(g_node_sum + (size_t)u * DIM);
        const float4* pv = reinterpret_cast<const float4*>(g_node_sum + (size_t)v * DIM);
        const float4* pwf = reinterpret_cast<const float4*>(g_wfg);
        const float4* pwb = reinterpret_cast<const float4*>(g_wbg);

        // Batch all loads first (12 independent LDG.128 -> high MLP)
        float4 em[4], nu[4], nv[4];
        #pragma unroll
        for (int i = 0; i < 4; ++i) {
            int cc = i * 4 + m;
            em[i] = pe[cc];
            nu[i] = pu[cc];
            nv[i] = pv[cc];
        }

        float t = 0.f;
        #pragma unroll
        for (int i = 0; i < 4; ++i) {
            int cc = i * 4 + m;
            float4 wf4 = pwf[cc], wb4 = pwb[cc];
            float4 au, av;
            au.x = (nu[i].x - em[i].x) * su; au.y = (nu[i].y - em[i].y) * su;
            au.z = (nu[i].z - em[i].z) * su; au.w = (nu[i].w - em[i].w) * su;
            av.x = (nv[i].x - em[i].x) * sv; av.y = (nv[i].y - em[i].y) * sv;
            av.z = (nv[i].z - em[i].z) * sv; av.w = (nv[i].w - em[i].w) * sv;
            t = fmaf(au.x, wf4.x, t); t = fmaf(au.y, wf4.y, t);
            t = fmaf(au.z, wf4.z, t); t = fmaf(au.w, wf4.w, t);
            t = fmaf(av.x, wb4.x, t); t = fmaf(av.y, wb4.y, t);
            t = fmaf(av.z, wb4.z, t); t = fmaf(av.w, wb4.w, t);
            float4 auq = make_float4(tf32r(au.x), tf32r(au.y), tf32r(au.z), tf32r(au.w));
            float4 avq = make_float4(tf32r(av.x), tf32r(av.y), tf32r(av.z), tf32r(av.w));
            *reinterpret_cast<float4*>(sAu + le * AST + cc * 4) = auq;
            *reinterpret_cast<float4*>(sAv + le * AST + cc * 4) = avq;
        }
        t += __shfl_xor_sync(0xffffffffu, t, 2);
        t += __shfl_xor_sync(0xffffffffu, t, 1);
        if (m == 0) {
            float gg = 1.f / (1.f + expf(-(t + g_cb)));
            sG[le] = gg;
        }
    }
    __syncthreads();        // the only barrier

    // Mainloop: warp tile 32 edges x 32 cols, both GEMMs.
    const int g  = lane >> 2;
    const int tg = lane & 3;
    const int m0 = (wid >> 1) * 32;
    const int nh = wid & 1;

    // ldmatrix lane->row mapping: row = lane&15, col-half = lane>>4 (4 floats)
    const int lrow  = lane & 15;
    const int lkoff = (lane >> 4) * 4;
    uint32_t aaddrU0 = smem_u32(sAu + (m0 + lrow) * AST + lkoff);
    uint32_t aaddrU1 = smem_u32(sAu + (m0 + 16 + lrow) * AST + lkoff);
    uint32_t aaddrV0 = smem_u32(sAv + (m0 + lrow) * AST + lkoff);
    uint32_t aaddrV1 = smem_u32(sAv + (m0 + 16 + lrow) * AST + lkoff);

    const float4* pF = reinterpret_cast<const float4*>(g_wfragF) + (nh * 8 * 32 + lane) * 2;
    const float4* pB = reinterpret_cast<const float4*>(g_wfragB) + (nh * 8 * 32 + lane) * 2;

    float dU[2][4][4] = {};
    float dV[2][4][4] = {};

    #pragma unroll
    for (int k0 = 0; k0 < 8; ++k0) {
        uint32_t aU[2][4], aV[2][4];
        ldm4(aU[0], aaddrU0 + k0 * 32);
        ldm4(aU[1], aaddrU1 + k0 * 32);
        ldm4(aV[0], aaddrV0 + k0 * 32);
        ldm4(aV[1], aaddrV1 + k0 * 32);

        float4 f0 = pF[k0 * 64 + 0], f1 = pF[k0 * 64 + 1];
        float4 b0 = pB[k0 * 64 + 0], b1 = pB[k0 * 64 + 1];
        uint32_t bF[4][2] = {
            {__float_as_uint(f0.x), __float_as_uint(f0.y)},
            {__float_as_uint(f0.z), __float_as_uint(f0.w)},
            {__float_as_uint(f1.x), __float_as_uint(f1.y)},
            {__float_as_uint(f1.z), __float_as_uint(f1.w)}};
        uint32_t bB[4][2] = {
            {__float_as_uint(b0.x), __float_as_uint(b0.y)},
            {__float_as_uint(b0.z), __float_as_uint(b0.w)},
            {__float_as_uint(b1.x), __float_as_uint(b1.y)},
            {__float_as_uint(b1.z), __float_as_uint(b1.w)}};

        #pragma unroll
        for (int nj = 0; nj < 4; ++nj) {
            mma8(dU[0][nj], aU[0], bF[nj]);
            mma8(dU[1][nj], aU[1], bF[nj]);
            mma8(dV[0][nj], aV[0], bB[nj]);
            mma8(dV[1][nj], aV[1], bB[nj]);
        }
    }

    // Epilogue directly from fragments: out = g*(dU+bf) + (1-g)*(dV+bb)
    const int ebase = blockIdx.x * TM;
    #pragma unroll
    for (int mi = 0; mi < 2; ++mi) {
        int r0 = m0 + mi * 16 + g;
        float g0 = sG[r0], g1 = sG[r0 + 8];
        float h0 = 1.f - g0, h1 = 1.f - g1;
        #pragma unroll
        for (int nj = 0; nj < 4; ++nj) {
            int col = nh * 32 + nj * 8 + 2 * tg;
            float bf0 = sBf[col], bf1 = sBf[col + 1];
            float bb0 = sBb[col], bb1 = sBb[col + 1];
            float2 o;
            o.x = g0 * (dU[mi][nj][0] + bf0) + h0 * (dV[mi][nj][0] + bb0);
            o.y = g0 * (dU[mi][nj][1] + bf1) + h0 * (dV[mi][nj][1] + bb1);
            *reinterpret_cast<float2*>(out + (size_t)(ebase + r0) * DIM + col) = o;
            o.x = g1 * (dU[mi][nj][2] + bf0) + h1 * (dV[mi][nj][2] + bb0);
            o.y = g1 * (dU[mi][nj][3] + bf1) + h1 * (dV[mi][nj][3] + bb1);
            *reinterpret_cast<float2*>(out + (size_t)(ebase + r0 + 8) * DIM + col) = o;
        }
    }
}

extern "C" void kernel_launch(void* const* d_in, const int* in_sizes, int n_in,
                              void* d_out, int out_size) {
    const float* emb = (const float*)d_in[0];
    const float* Wf  = (const float*)d_in[1];
    const float* bf  = (const float*)d_in[2];
    const float* Wb  = (const float*)d_in[3];
    const float* bb  = (const float*)d_in[4];
    const float* Wg  = (const float*)d_in[5];
    const float* bg  = (const float*)d_in[6];
    const void*  idx = d_in[7];
    float* out = (float*)d_out;

    (void)in_sizes; (void)n_in; (void)out_size;

    detect_kernel<<<1, 256>>>((const int*)idx);

    int zthreads = (N_NODES * DIM) / 4;
    zero_kernel<<<(zthreads + 255) / 256, 256>>>();

    prep_kernel<<<1, 256>>>(Wf, Wb, bf, bb, Wg, bg);

    int sthreads = NE * 16;
    scatter_kernel<<<(sthreads + 255) / 256, 256>>>(emb, idx);

    int smem = (2 * TM * AST + 2 * DIM + TM) * (int)sizeof(float);   // 35584
    cudaFuncSetAttribute(fused_kernel,
                         cudaFuncAttributeMaxDynamicSharedMemorySize, smem);
    fused_kernel<<<NE / TM, 128, smem>>>(emb, bf, bb, idx, out);
}